// round 13
// baseline (speedup 1.0000x reference)
#include <cuda_runtime.h>
#include <math.h>

typedef unsigned long long ull;

#define NBC  6          // B*C
#define NBLK 384        // 64 blocks per bc; block = one 8x8x8 L2-cell region = one L5 cell

// Static __device__ scratch (allocation-free). Zero-init; finalize resets for replay.
__device__ double       g_acc[NBC][54];
__device__ unsigned int g_ctr;

// ---- packed f32x2 helpers (Blackwell 2xFP32; ptxas won't auto-emit) ----
__device__ __forceinline__ ull pk2(float lo, float hi) {
    ull r; asm("mov.b64 %0, {%1, %2};" : "=l"(r) : "f"(lo), "f"(hi)); return r;
}
__device__ __forceinline__ float2 upk2(ull v) {
    float2 f; asm("mov.b64 {%0, %1}, %2;" : "=f"(f.x), "=f"(f.y) : "l"(v)); return f;
}
__device__ __forceinline__ ull add2(ull a, ull b) {
    ull r; asm("add.rn.f32x2 %0, %1, %2;" : "=l"(r) : "l"(a), "l"(b)); return r;
}
__device__ __forceinline__ ull mul2(ull a, ull b) {
    ull r; asm("mul.rn.f32x2 %0, %1, %2;" : "=l"(r) : "l"(a), "l"(b)); return r;
}
__device__ __forceinline__ ull fma2(ull a, ull b, ull c) {
    ull r; asm("fma.rn.f32x2 %0, %1, %2, %3;" : "=l"(r) : "l"(a), "l"(b), "l"(c)); return r;
}
__device__ __forceinline__ float rcpa(float x) {
    float r; asm("rcp.approx.f32 %0, %1;" : "=f"(r) : "f"(x)); return r;
}
__device__ __forceinline__ float lg2a(float x) {
    float r; asm("lg2.approx.f32 %0, %1;" : "=f"(r) : "f"(x)); return r;
}

// Packed pair accumulation, both values nonzero. No S1 (stat0 redundant: derived
// from L5 sums). 3 MUFU per pair via rcp-of-product trick.
__device__ __forceinline__ void acc_pair_t(ull x, ull& S2, ull& S3, ull& S4,
                                           ull& S5, float& Sm1, float& Sm2,
                                           float& T2a, float& T2b) {
    float2 f = upk2(x);
    float r  = rcpa(f.x * f.y);             // MUFU.RCP
    float la = lg2a(f.x), lb = lg2a(f.y);   // 2x MUFU.LG2
    ull xx = mul2(x, x);
    S2 = add2(S2, xx);
    ull x3 = mul2(xx, x);
    S3 = add2(S3, x3);
    S4 = fma2(xx, xx, S4);
    S5 = fma2(x3, xx, S5);
    float2 fx = upk2(xx);
    Sm1 = fmaf(f.x + f.y, r, Sm1);
    Sm2 = fmaf(fx.x + fx.y, r * r, Sm2);
    T2a = fmaf(f.x, la, T2a);
    T2b = fmaf(f.y, lb, T2b);
}

// Scalar zero-skipping accumulation (rare slow path). No S1.
__device__ __forceinline__ void acc_one(float v, ull& S2, ull& S3, ull& S4,
                                        ull& S5, float& Sm1, float& Sm2, float& T2a,
                                        float& cnt) {
    if (v != 0.0f) {
        float inv = rcpa(v), lg = lg2a(v);
        float v2 = v * v, v3 = v2 * v;
        S2 = add2(S2, pk2(v2, 0.f));
        S3 = add2(S3, pk2(v3, 0.f));
        S4 = add2(S4, pk2(v2 * v2, 0.f));
        S5 = add2(S5, pk2(v3 * v2, 0.f));
        Sm1 += inv;
        Sm2 += inv * inv;
        T2a = fmaf(v, lg, T2a);
        cnt += 1.0f;
    }
}

// Scalar zero-skipping stats WITHOUT stat0 (S1 redundant at L1..L4).
__device__ __forceinline__ void acc_scalar8(float v, float* st) {
    if (v != 0.0f) {
        float inv = rcpa(v), lg = lg2a(v);
        float v2 = v * v, v3 = v2 * v;
        st[1] += v2;  st[2] += v3;
        st[3] += v2 * v2;  st[4] += v3 * v2;
        st[5] += inv;  st[6] += inv * inv;
        st[7] += v * lg;  st[8] += 1.0f;
    }
}

// Full 9-stat version (L5 only; one call per block).
__device__ __forceinline__ void acc_scalar9(float v, float* st) {
    if (v != 0.0f) {
        float inv = rcpa(v), lg = lg2a(v);
        float v2 = v * v, v3 = v2 * v;
        st[0] += v;
        st[1] += v2;  st[2] += v3;
        st[3] += v2 * v2;  st[4] += v3 * v2;
        st[5] += inv;  st[6] += inv * inv;
        st[7] += v * lg;  st[8] += 1.0f;
    }
}

__device__ __forceinline__ float wred32(float v) {
#pragma unroll
    for (int o = 16; o; o >>= 1) v += __shfl_down_sync(0xFFFFFFFFu, v, o);
    return v;
}

// One 4^3 cell: L0 stats on 64 voxels, L1 stats on 8 octant sums. Returns cell sum.
__device__ __forceinline__ float do_cell(const float* __restrict__ cbase,
                                         ull& S2, ull& S3, ull& S4, ull& S5,
                                         float& Sm1, float& Sm2, float& T2a, float& T2b,
                                         float& cnt, float* st1) {
    float l2v = 0.0f;
#pragma unroll
    for (int dzp = 0; dzp < 4; dzp += 2) {
        const float* q = cbase + (dzp << 14);
        // 8 rows of 4 floats (MLP=8 LDG.128)
        ulonglong2 ua = *reinterpret_cast<const ulonglong2*>(q);
        ulonglong2 ub = *reinterpret_cast<const ulonglong2*>(q + 128);
        ulonglong2 uc = *reinterpret_cast<const ulonglong2*>(q + 256);
        ulonglong2 ud = *reinterpret_cast<const ulonglong2*>(q + 384);
        ulonglong2 ue = *reinterpret_cast<const ulonglong2*>(q + 16384);
        ulonglong2 uf = *reinterpret_cast<const ulonglong2*>(q + 16512);
        ulonglong2 ug = *reinterpret_cast<const ulonglong2*>(q + 16640);
        ulonglong2 uh = *reinterpret_cast<const ulonglong2*>(q + 16768);

        // L1 (2x2x2) sums
        ull sl0 = add2(add2(ua.x, ub.x), add2(ue.x, uf.x));
        ull sl1 = add2(add2(uc.x, ud.x), add2(ug.x, uh.x));
        ull sh0 = add2(add2(ua.y, ub.y), add2(ue.y, uf.y));
        ull sh1 = add2(add2(uc.y, ud.y), add2(ug.y, uh.y));
        float2 f;
        f = upk2(sl0); float l100 = f.x + f.y;
        f = upk2(sl1); float l101 = f.x + f.y;
        f = upk2(sh0); float l110 = f.x + f.y;
        f = upk2(sh1); float l111 = f.x + f.y;

        // zero test: product of all 32 voxels (underflow -> safe slow path)
        ull p = mul2(mul2(mul2(ua.x, ua.y), mul2(ub.x, ub.y)),
                     mul2(mul2(uc.x, uc.y), mul2(ud.x, ud.y)));
        p = mul2(p, mul2(mul2(ue.x, ue.y), mul2(uf.x, uf.y)));
        p = mul2(p, mul2(mul2(ug.x, ug.y), mul2(uh.x, uh.y)));
        f = upk2(p);
        if (f.x * f.y != 0.0f) {
            acc_pair_t(ua.x, S2, S3, S4, S5, Sm1, Sm2, T2a, T2b);
            acc_pair_t(ua.y, S2, S3, S4, S5, Sm1, Sm2, T2a, T2b);
            acc_pair_t(ub.x, S2, S3, S4, S5, Sm1, Sm2, T2a, T2b);
            acc_pair_t(ub.y, S2, S3, S4, S5, Sm1, Sm2, T2a, T2b);
            acc_pair_t(uc.x, S2, S3, S4, S5, Sm1, Sm2, T2a, T2b);
            acc_pair_t(uc.y, S2, S3, S4, S5, Sm1, Sm2, T2a, T2b);
            acc_pair_t(ud.x, S2, S3, S4, S5, Sm1, Sm2, T2a, T2b);
            acc_pair_t(ud.y, S2, S3, S4, S5, Sm1, Sm2, T2a, T2b);
            acc_pair_t(ue.x, S2, S3, S4, S5, Sm1, Sm2, T2a, T2b);
            acc_pair_t(ue.y, S2, S3, S4, S5, Sm1, Sm2, T2a, T2b);
            acc_pair_t(uf.x, S2, S3, S4, S5, Sm1, Sm2, T2a, T2b);
            acc_pair_t(uf.y, S2, S3, S4, S5, Sm1, Sm2, T2a, T2b);
            acc_pair_t(ug.x, S2, S3, S4, S5, Sm1, Sm2, T2a, T2b);
            acc_pair_t(ug.y, S2, S3, S4, S5, Sm1, Sm2, T2a, T2b);
            acc_pair_t(uh.x, S2, S3, S4, S5, Sm1, Sm2, T2a, T2b);
            acc_pair_t(uh.y, S2, S3, S4, S5, Sm1, Sm2, T2a, T2b);
            cnt += 32.0f;
        } else {
            ull us[16] = {ua.x, ua.y, ub.x, ub.y, uc.x, uc.y, ud.x, ud.y,
                          ue.x, ue.y, uf.x, uf.y, ug.x, ug.y, uh.x, uh.y};
#pragma unroll 4
            for (int j = 0; j < 16; j++) {
                float2 vv = upk2(us[j]);
                acc_one(vv.x, S2, S3, S4, S5, Sm1, Sm2, T2a, cnt);
                acc_one(vv.y, S2, S3, S4, S5, Sm1, Sm2, T2a, cnt);
            }
        }
        acc_scalar8(l100, st1);
        acc_scalar8(l101, st1);
        acc_scalar8(l110, st1);
        acc_scalar8(l111, st1);
        l2v += (l100 + l101) + (l110 + l111);
    }
    return l2v;
}

__global__ void __launch_bounds__(256, 3) fractal_kernel(const float* __restrict__ img,
                                                         const int* __restrict__ bounds,
                                                         float* __restrict__ out) {
    const int b   = blockIdx.x;
    const int tid = threadIdx.x;
    const int bc  = b >> 6, tile = b & 63;
    const int tw = tile & 3, th = (tile >> 2) & 3, td = tile >> 4;
    const int cw = tid & 7, ch = (tid >> 3) & 7, cd0 = tid >> 6;

    __shared__ float l2s[512];
    __shared__ float l3s[64];
    __shared__ float w0[8][9], w1[8][9], w2[8][9], w3[2][9];
    __shared__ float bs[54];
    __shared__ float accF[NBC][54];
    __shared__ unsigned int flag;

    ull S2 = 0, S3 = 0, S4 = 0, S5 = 0;
    float Sm1 = 0.f, Sm2 = 0.f, T2a = 0.f, T2b = 0.f, cnt = 0.f;
    float st1[9];
#pragma unroll
    for (int j = 0; j < 9; j++) st1[j] = 0.f;

    const float* base0 = img + ((size_t)bc << 21) + (((th << 3) + ch) << 9)
                       + (((tw << 3) + cw) << 2);
    float l2v0 = do_cell(base0 + ((size_t)((td << 3) + cd0) << 16),
                         S2, S3, S4, S5, Sm1, Sm2, T2a, T2b, cnt, st1);
    float l2v1 = do_cell(base0 + ((size_t)((td << 3) + cd0 + 4) << 16),
                         S2, S3, S4, S5, Sm1, Sm2, T2a, T2b, cnt, st1);

    // L2 stats out of the hot loop
    float st2[9];
#pragma unroll
    for (int j = 0; j < 9; j++) st2[j] = 0.f;
    acc_scalar8(l2v0, st2);
    acc_scalar8(l2v1, st2);

    l2s[tid]       = l2v0;
    l2s[tid + 256] = l2v1;
    __syncthreads();

    // L3: 64 threads pool 2x2x2 from l2s (8x8x8)
    float st3[9];
    if (tid < 64) {
#pragma unroll
        for (int j = 0; j < 9; j++) st3[j] = 0.f;
        int jw = tid & 3, jh = (tid >> 2) & 3, jd = tid >> 4;
        int b3 = (jd << 7) | (jh << 4) | (jw << 1);
        float l3v = 0.f;
#pragma unroll
        for (int di = 0; di < 2; di++)
#pragma unroll
            for (int hi = 0; hi < 2; hi++)
#pragma unroll
                for (int wi = 0; wi < 2; wi++)
                    l3v += l2s[b3 + (di << 6) + (hi << 3) + wi];
        acc_scalar8(l3v, st3);
        l3s[tid] = l3v;
    }
    __syncthreads();

    // L4: 8 threads pool; L5 = block total (full 9 stats incl. S1 -> b)
    if (tid < 8) {
        int mw = tid & 1, mh = (tid >> 1) & 1, md = tid >> 2;
        int b4 = (md << 5) | (mh << 3) | (mw << 1);
        float l4v = 0.f;
#pragma unroll
        for (int di = 0; di < 2; di++)
#pragma unroll
            for (int hi = 0; hi < 2; hi++)
#pragma unroll
                for (int wi = 0; wi < 2; wi++)
                    l4v += l3s[b4 + (di << 4) + (hi << 2) + wi];
        float st4[9];
#pragma unroll
        for (int j = 0; j < 9; j++) st4[j] = 0.f;
        acc_scalar8(l4v, st4);
        float l5v = l4v;
#pragma unroll
        for (int o = 4; o; o >>= 1) {
            l5v += __shfl_down_sync(0xFFu, l5v, o);
#pragma unroll
            for (int j = 0; j < 9; j++) st4[j] += __shfl_down_sync(0xFFu, st4[j], o);
        }
        if (tid == 0) {
#pragma unroll
            for (int j = 0; j < 9; j++) bs[36 + j] = st4[j];   // L4
            float st5[9];
#pragma unroll
            for (int j = 0; j < 9; j++) st5[j] = 0.f;
            acc_scalar9(l5v, st5);                              // incl. stat0 = b part
#pragma unroll
            for (int j = 0; j < 9; j++) bs[45 + j] = st5[j];   // L5
        }
    }

    // warp staging: L0/L1/L2 across 8 warps, L3 across warps 0,1 (stat0 lanes are 0)
    {
        float st0[9];
        float2 f;
        st0[0] = 0.f;
        f = upk2(S2); st0[1] = f.x + f.y;
        f = upk2(S3); st0[2] = f.x + f.y;
        f = upk2(S4); st0[3] = f.x + f.y;
        f = upk2(S5); st0[4] = f.x + f.y;
        st0[5] = Sm1; st0[6] = Sm2; st0[7] = T2a + T2b; st0[8] = cnt;
        int lane = tid & 31, warp = tid >> 5;
#pragma unroll
        for (int j = 0; j < 9; j++) {
            float a0 = wred32(st0[j]);
            float a1 = wred32(st1[j]);
            float a2 = wred32(st2[j]);
            if (lane == 0) { w0[warp][j] = a0; w1[warp][j] = a1; w2[warp][j] = a2; }
        }
        if (tid < 64) {
#pragma unroll
            for (int j = 0; j < 9; j++) {
                float a3 = wred32(st3[j]);
                if (lane == 0) w3[warp][j] = a3;
            }
        }
    }
    __syncthreads();

    if (tid < 9) {
        float s = 0.f;
#pragma unroll
        for (int w = 0; w < 8; w++) s += w0[w][tid];
        bs[tid] = s;
    } else if (tid >= 32 && tid < 41) {
        int j = tid - 32;
        float s = 0.f;
#pragma unroll
        for (int w = 0; w < 8; w++) s += w1[w][j];
        bs[9 + j] = s;
    } else if (tid >= 64 && tid < 73) {
        int j = tid - 64;
        float s = 0.f;
#pragma unroll
        for (int w = 0; w < 8; w++) s += w2[w][j];
        bs[18 + j] = s;
    } else if (tid >= 96 && tid < 105) {
        int j = tid - 96;
        bs[27 + j] = w3[0][j] + w3[1][j];
    }
    __syncthreads();

    // global accumulate (RED.ADD.F64, 54 spread addresses) + arrival
    if (tid < 54) {
        atomicAdd(&g_acc[bc][tid], (double)bs[tid]);
        __threadfence();
    }
    __syncthreads();
    if (tid == 0) flag = (atomicAdd(&g_ctr, 1u) == NBLK - 1) ? 1u : 0u;
    __syncthreads();
    if (!flag) return;
    if (tid == 0) __threadfence();
    __syncthreads();

    // ================= FINALIZE (last block) =================
    for (int u = tid; u < NBC * 54; u += 256)
        accF[u / 54][u % 54] = (float)g_acc[u / 54][u % 54];
    __syncthreads();
    // reset for next graph replay
    for (int u = tid; u < NBC * 54; u += 256) g_acc[u / 54][u % 54] = 0.0;
    if (tid == 0) g_ctr = 0;

    if (tid >= NBC * 8) return;
    int obc = tid >> 3;
    int k   = bounds[tid & 7];

    const float LN2 = 0.69314718055994531f;
    float bsum = accF[obc][45];             // L5 S1 = total image sum (pooling-invariant)
    float lnb  = logf(bsum);

    float sp = 0.0f, spq = 0.0f;
    for (int s = 0; s < 6; s++) {
        const float* a = &accF[obc][s * 9];
        float pv;
        if (k == 1) {
            pv = (a[7] * LN2) / bsum - lnb;
        } else if (k == 0) {
            pv = logf(a[8]);
        } else {
            float S;
            switch (k) {
                case  2: S = a[1]; break;
                case  3: S = a[2]; break;
                case  4: S = a[3]; break;
                case  5: S = a[4]; break;
                case -1: S = a[5]; break;
                case -2: S = a[6]; break;
                default: S = __int_as_float(0x7FC00000); break;
            }
            pv = logf(S) - (float)k * lnb;
        }
        sp  += pv;
        spq += pv * ((float)s * LN2);
    }
    const float qs  = 15.0f * LN2;
    const float q2s = 55.0f * LN2 * LN2;
    const float den = 6.0f * q2s - qs * qs;
    float aa = (k == 1) ? 1.0f : 1.0f / (float)(k - 1);
    out[tid] = aa * (6.0f * spq - sp * qs) / den;
}

extern "C" void kernel_launch(void* const* d_in, const int* in_sizes, int n_in,
                              void* d_out, int out_size) {
    const float* img    = (const float*)d_in[0];
    const int*   bounds = (const int*)d_in[1];
    float*       out    = (float*)d_out;

    fractal_kernel<<<NBLK, 256>>>(img, bounds, out);
}

// round 14
// speedup vs baseline: 1.0102x; 1.0102x over previous
#include <cuda_runtime.h>
#include <math.h>

typedef unsigned long long ull;

#define NBC  6          // B*C
#define NBLK 384        // 64 blocks per bc; block = one 8x8x8 L2-cell region = one L5 cell

// Static __device__ scratch (allocation-free). Zero-init; finalize resets for replay.
__device__ double       g_acc[NBC][54];
__device__ unsigned int g_ctr;

// ---- packed f32x2 helpers (Blackwell 2xFP32; ptxas won't auto-emit) ----
__device__ __forceinline__ ull pk2(float lo, float hi) {
    ull r; asm("mov.b64 %0, {%1, %2};" : "=l"(r) : "f"(lo), "f"(hi)); return r;
}
__device__ __forceinline__ float2 upk2(ull v) {
    float2 f; asm("mov.b64 {%0, %1}, %2;" : "=f"(f.x), "=f"(f.y) : "l"(v)); return f;
}
__device__ __forceinline__ ull add2(ull a, ull b) {
    ull r; asm("add.rn.f32x2 %0, %1, %2;" : "=l"(r) : "l"(a), "l"(b)); return r;
}
__device__ __forceinline__ ull mul2(ull a, ull b) {
    ull r; asm("mul.rn.f32x2 %0, %1, %2;" : "=l"(r) : "l"(a), "l"(b)); return r;
}
__device__ __forceinline__ ull fma2(ull a, ull b, ull c) {
    ull r; asm("fma.rn.f32x2 %0, %1, %2, %3;" : "=l"(r) : "l"(a), "l"(b), "l"(c)); return r;
}
__device__ __forceinline__ float rcpa(float x) {
    float r; asm("rcp.approx.f32 %0, %1;" : "=f"(r) : "f"(x)); return r;
}
__device__ __forceinline__ float lg2a(float x) {
    float r; asm("lg2.approx.f32 %0, %1;" : "=f"(r) : "f"(x)); return r;
}
__device__ __forceinline__ ulonglong2 ld2(const float* p) {
    return *reinterpret_cast<const ulonglong2*>(p);
}

// Packed pair accumulation, both values nonzero. 3 MUFU via rcp-of-product trick.
__device__ __forceinline__ void acc_pair_t(ull x, ull& S2, ull& S3, ull& S4,
                                           ull& S5, float& Sm1, float& Sm2,
                                           float& T2a, float& T2b) {
    float2 f = upk2(x);
    float r  = rcpa(f.x * f.y);             // MUFU.RCP
    float la = lg2a(f.x), lb = lg2a(f.y);   // 2x MUFU.LG2
    ull xx = mul2(x, x);
    S2 = add2(S2, xx);
    ull x3 = mul2(xx, x);
    S3 = add2(S3, x3);
    S4 = fma2(xx, xx, S4);
    S5 = fma2(x3, xx, S5);
    float2 fx = upk2(xx);
    Sm1 = fmaf(f.x + f.y, r, Sm1);
    Sm2 = fmaf(fx.x + fx.y, r * r, Sm2);
    T2a = fmaf(f.x, la, T2a);
    T2b = fmaf(f.y, lb, T2b);
}

// Scalar zero-skipping accumulation (rare slow path).
__device__ __forceinline__ void acc_one(float v, ull& S2, ull& S3, ull& S4,
                                        ull& S5, float& Sm1, float& Sm2, float& T2a,
                                        float& cnt) {
    if (v != 0.0f) {
        float inv = rcpa(v), lg = lg2a(v);
        float v2 = v * v, v3 = v2 * v;
        S2 = add2(S2, pk2(v2, 0.f));
        S3 = add2(S3, pk2(v3, 0.f));
        S4 = add2(S4, pk2(v2 * v2, 0.f));
        S5 = add2(S5, pk2(v3 * v2, 0.f));
        Sm1 += inv;
        Sm2 += inv * inv;
        T2a = fmaf(v, lg, T2a);
        cnt += 1.0f;
    }
}

// Stats WITHOUT stat0 (S1 redundant at L1..L4; derived from L5 sums).
__device__ __forceinline__ void acc_scalar8(float v, float* st) {
    if (v != 0.0f) {
        float inv = rcpa(v), lg = lg2a(v);
        float v2 = v * v, v3 = v2 * v;
        st[1] += v2;  st[2] += v3;
        st[3] += v2 * v2;  st[4] += v3 * v2;
        st[5] += inv;  st[6] += inv * inv;
        st[7] += v * lg;  st[8] += 1.0f;
    }
}

// Full 9-stat version (L5 only; one call per block).
__device__ __forceinline__ void acc_scalar9(float v, float* st) {
    if (v != 0.0f) {
        float inv = rcpa(v), lg = lg2a(v);
        float v2 = v * v, v3 = v2 * v;
        st[0] += v;
        st[1] += v2;  st[2] += v3;
        st[3] += v2 * v2;  st[4] += v3 * v2;
        st[5] += inv;  st[6] += inv * inv;
        st[7] += v * lg;  st[8] += 1.0f;
    }
}

__device__ __forceinline__ float wred32(float v) {
#pragma unroll
    for (int o = 16; o; o >>= 1) v += __shfl_down_sync(0xFFFFFFFFu, v, o);
    return v;
}

// One plane (4 rows x 4 floats = 16 voxels): L0 stats + packed row-pair partials.
__device__ __forceinline__ void plane_acc(ulonglong2 A, ulonglong2 B,
                                          ulonglong2 C, ulonglong2 D,
                                          ull& S2, ull& S3, ull& S4, ull& S5,
                                          float& Sm1, float& Sm2, float& T2a, float& T2b,
                                          float& cnt,
                                          ull& r0, ull& r1, ull& r2, ull& r3) {
    r0 = add2(A.x, B.x);   // hy0+hy1, w01
    r1 = add2(C.x, D.x);   // hy2+hy3, w01
    r2 = add2(A.y, B.y);   // hy0+hy1, w23
    r3 = add2(C.y, D.y);   // hy2+hy3, w23
    // zero test over 16 voxels (underflow -> safe exact slow path)
    ull pr = mul2(mul2(mul2(A.x, A.y), mul2(B.x, B.y)),
                  mul2(mul2(C.x, C.y), mul2(D.x, D.y)));
    float2 pf = upk2(pr);
    if (pf.x * pf.y != 0.0f) {
        acc_pair_t(A.x, S2, S3, S4, S5, Sm1, Sm2, T2a, T2b);
        acc_pair_t(A.y, S2, S3, S4, S5, Sm1, Sm2, T2a, T2b);
        acc_pair_t(B.x, S2, S3, S4, S5, Sm1, Sm2, T2a, T2b);
        acc_pair_t(B.y, S2, S3, S4, S5, Sm1, Sm2, T2a, T2b);
        acc_pair_t(C.x, S2, S3, S4, S5, Sm1, Sm2, T2a, T2b);
        acc_pair_t(C.y, S2, S3, S4, S5, Sm1, Sm2, T2a, T2b);
        acc_pair_t(D.x, S2, S3, S4, S5, Sm1, Sm2, T2a, T2b);
        acc_pair_t(D.y, S2, S3, S4, S5, Sm1, Sm2, T2a, T2b);
        cnt += 16.0f;
    } else {
        ull us[8] = {A.x, A.y, B.x, B.y, C.x, C.y, D.x, D.y};
#pragma unroll 4
        for (int j = 0; j < 8; j++) {
            float2 vv = upk2(us[j]);
            acc_one(vv.x, S2, S3, S4, S5, Sm1, Sm2, T2a, cnt);
            acc_one(vv.y, S2, S3, S4, S5, Sm1, Sm2, T2a, cnt);
        }
    }
}

__global__ void __launch_bounds__(256, 3) fractal_kernel(const float* __restrict__ img,
                                                         const int* __restrict__ bounds,
                                                         float* __restrict__ out) {
    const int b   = blockIdx.x;
    const int tid = threadIdx.x;
    const int bc  = b >> 6, tile = b & 63;
    const int tw = tile & 3, th = (tile >> 2) & 3, td = tile >> 4;
    const int cw = tid & 7, ch = (tid >> 3) & 7, cd0 = tid >> 6;

    __shared__ float l2s[512];
    __shared__ float l3s[64];
    __shared__ float w0[8][9], w1[8][9], w2[8][9], w3[2][9];
    __shared__ float bs[54];
    __shared__ float accF[NBC][54];
    __shared__ unsigned int flag;

    ull S2 = 0, S3 = 0, S4 = 0, S5 = 0;
    float Sm1 = 0.f, Sm2 = 0.f, T2a = 0.f, T2b = 0.f, cnt = 0.f;
    float st1[9];
#pragma unroll
    for (int j = 0; j < 9; j++) st1[j] = 0.f;
    float l2v0 = 0.f, l2v1 = 0.f;

    // cell 0 base; cell 1 is +4 d-planes of cells = +2^18 floats
    const float* cb0 = img + ((size_t)bc << 21) + (((size_t)(td << 3) + cd0) << 16)
                     + (((th << 3) + ch) << 9) + (((tw << 3) + cw) << 2);

    // ---- software-pipelined main loop: 4 dz-pairs x 2 planes ----
    ulonglong2 A, B, C, D, N0, N1, N2, N3;
    A = ld2(cb0); B = ld2(cb0 + 128); C = ld2(cb0 + 256); D = ld2(cb0 + 384);
#pragma unroll 1
    for (int pp = 0; pp < 4; pp++) {
        // pair pp: cell = pp>>1 (offset (pp&2)<<17), dzp = (pp&1)*2 (offset (pp&1)<<15)
        const float* pb = cb0 + ((pp & 2) << 17) + ((pp & 1) << 15);
        const float* po = pb + 16384;                         // odd plane (dz+1)
        N0 = ld2(po); N1 = ld2(po + 128); N2 = ld2(po + 256); N3 = ld2(po + 384);

        ull e0, e1, e2, e3;
        plane_acc(A, B, C, D, S2, S3, S4, S5, Sm1, Sm2, T2a, T2b, cnt, e0, e1, e2, e3);

        if (pp < 3) {                                          // prefetch next even plane
            int pn = pp + 1;
            const float* q = cb0 + ((pn & 2) << 17) + ((pn & 1) << 15);
            A = ld2(q); B = ld2(q + 128); C = ld2(q + 256); D = ld2(q + 384);
        }

        ull o0, o1, o2, o3;
        plane_acc(N0, N1, N2, N3, S2, S3, S4, S5, Sm1, Sm2, T2a, T2b, cnt, o0, o1, o2, o3);

        // complete the 4 L1 octants of this dz-pair
        float2 f0 = upk2(add2(e0, o0));
        float2 f1 = upk2(add2(e1, o1));
        float2 f2 = upk2(add2(e2, o2));
        float2 f3 = upk2(add2(e3, o3));
        float l00 = f0.x + f0.y, l01 = f1.x + f1.y;
        float l10 = f2.x + f2.y, l11 = f3.x + f3.y;
        acc_scalar8(l00, st1);
        acc_scalar8(l01, st1);
        acc_scalar8(l10, st1);
        acc_scalar8(l11, st1);
        float addv = (l00 + l01) + (l10 + l11);
        if (pp < 2) l2v0 += addv; else l2v1 += addv;
    }

    // L2 stats (2 values per thread)
    float st2[9];
#pragma unroll
    for (int j = 0; j < 9; j++) st2[j] = 0.f;
    acc_scalar8(l2v0, st2);
    acc_scalar8(l2v1, st2);

    l2s[tid]       = l2v0;
    l2s[tid + 256] = l2v1;
    __syncthreads();

    // L3: 64 threads pool 2x2x2 from l2s (8x8x8)
    float st3[9];
    if (tid < 64) {
#pragma unroll
        for (int j = 0; j < 9; j++) st3[j] = 0.f;
        int jw = tid & 3, jh = (tid >> 2) & 3, jd = tid >> 4;
        int b3 = (jd << 7) | (jh << 4) | (jw << 1);
        float l3v = 0.f;
#pragma unroll
        for (int di = 0; di < 2; di++)
#pragma unroll
            for (int hi = 0; hi < 2; hi++)
#pragma unroll
                for (int wi = 0; wi < 2; wi++)
                    l3v += l2s[b3 + (di << 6) + (hi << 3) + wi];
        acc_scalar8(l3v, st3);
        l3s[tid] = l3v;
    }
    __syncthreads();

    // L4: 8 threads pool; L5 = block total (full 9 stats incl. S1 -> b)
    if (tid < 8) {
        int mw = tid & 1, mh = (tid >> 1) & 1, md = tid >> 2;
        int b4 = (md << 5) | (mh << 3) | (mw << 1);
        float l4v = 0.f;
#pragma unroll
        for (int di = 0; di < 2; di++)
#pragma unroll
            for (int hi = 0; hi < 2; hi++)
#pragma unroll
                for (int wi = 0; wi < 2; wi++)
                    l4v += l3s[b4 + (di << 4) + (hi << 2) + wi];
        float st4[9];
#pragma unroll
        for (int j = 0; j < 9; j++) st4[j] = 0.f;
        acc_scalar8(l4v, st4);
        float l5v = l4v;
#pragma unroll
        for (int o = 4; o; o >>= 1) {
            l5v += __shfl_down_sync(0xFFu, l5v, o);
#pragma unroll
            for (int j = 0; j < 9; j++) st4[j] += __shfl_down_sync(0xFFu, st4[j], o);
        }
        if (tid == 0) {
#pragma unroll
            for (int j = 0; j < 9; j++) bs[36 + j] = st4[j];   // L4
            float st5[9];
#pragma unroll
            for (int j = 0; j < 9; j++) st5[j] = 0.f;
            acc_scalar9(l5v, st5);                              // incl. stat0 = b part
#pragma unroll
            for (int j = 0; j < 9; j++) bs[45 + j] = st5[j];   // L5
        }
    }

    // warp staging: L0/L1/L2 across 8 warps, L3 across warps 0,1
    {
        float st0[9];
        float2 f;
        st0[0] = 0.f;
        f = upk2(S2); st0[1] = f.x + f.y;
        f = upk2(S3); st0[2] = f.x + f.y;
        f = upk2(S4); st0[3] = f.x + f.y;
        f = upk2(S5); st0[4] = f.x + f.y;
        st0[5] = Sm1; st0[6] = Sm2; st0[7] = T2a + T2b; st0[8] = cnt;
        int lane = tid & 31, warp = tid >> 5;
#pragma unroll
        for (int j = 0; j < 9; j++) {
            float a0 = wred32(st0[j]);
            float a1 = wred32(st1[j]);
            float a2 = wred32(st2[j]);
            if (lane == 0) { w0[warp][j] = a0; w1[warp][j] = a1; w2[warp][j] = a2; }
        }
        if (tid < 64) {
#pragma unroll
            for (int j = 0; j < 9; j++) {
                float a3 = wred32(st3[j]);
                if (lane == 0) w3[warp][j] = a3;
            }
        }
    }
    __syncthreads();

    if (tid < 9) {
        float s = 0.f;
#pragma unroll
        for (int w = 0; w < 8; w++) s += w0[w][tid];
        bs[tid] = s;
    } else if (tid >= 32 && tid < 41) {
        int j = tid - 32;
        float s = 0.f;
#pragma unroll
        for (int w = 0; w < 8; w++) s += w1[w][j];
        bs[9 + j] = s;
    } else if (tid >= 64 && tid < 73) {
        int j = tid - 64;
        float s = 0.f;
#pragma unroll
        for (int w = 0; w < 8; w++) s += w2[w][j];
        bs[18 + j] = s;
    } else if (tid >= 96 && tid < 105) {
        int j = tid - 96;
        bs[27 + j] = w3[0][j] + w3[1][j];
    }
    __syncthreads();

    // global accumulate (RED.ADD.F64, 54 spread addresses) + arrival
    if (tid < 54) {
        atomicAdd(&g_acc[bc][tid], (double)bs[tid]);
        __threadfence();
    }
    __syncthreads();
    if (tid == 0) flag = (atomicAdd(&g_ctr, 1u) == NBLK - 1) ? 1u : 0u;
    __syncthreads();
    if (!flag) return;
    if (tid == 0) __threadfence();
    __syncthreads();

    // ================= FINALIZE (last block) =================
    for (int u = tid; u < NBC * 54; u += 256)
        accF[u / 54][u % 54] = (float)g_acc[u / 54][u % 54];
    __syncthreads();
    // reset for next graph replay
    for (int u = tid; u < NBC * 54; u += 256) g_acc[u / 54][u % 54] = 0.0;
    if (tid == 0) g_ctr = 0;

    if (tid >= NBC * 8) return;
    int obc = tid >> 3;
    int k   = bounds[tid & 7];

    const float LN2 = 0.69314718055994531f;
    float bsum = accF[obc][45];             // L5 S1 = total image sum (pooling-invariant)
    float lnb  = logf(bsum);

    float sp = 0.0f, spq = 0.0f;
    for (int s = 0; s < 6; s++) {
        const float* a = &accF[obc][s * 9];
        float pv;
        if (k == 1) {
            pv = (a[7] * LN2) / bsum - lnb;
        } else if (k == 0) {
            pv = logf(a[8]);
        } else {
            float S;
            switch (k) {
                case  2: S = a[1]; break;
                case  3: S = a[2]; break;
                case  4: S = a[3]; break;
                case  5: S = a[4]; break;
                case -1: S = a[5]; break;
                case -2: S = a[6]; break;
                default: S = __int_as_float(0x7FC00000); break;
            }
            pv = logf(S) - (float)k * lnb;
        }
        sp  += pv;
        spq += pv * ((float)s * LN2);
    }
    const float qs  = 15.0f * LN2;
    const float q2s = 55.0f * LN2 * LN2;
    const float den = 6.0f * q2s - qs * qs;
    float aa = (k == 1) ? 1.0f : 1.0f / (float)(k - 1);
    out[tid] = aa * (6.0f * spq - sp * qs) / den;
}

extern "C" void kernel_launch(void* const* d_in, const int* in_sizes, int n_in,
                              void* d_out, int out_size) {
    const float* img    = (const float*)d_in[0];
    const int*   bounds = (const int*)d_in[1];
    float*       out    = (float*)d_out;

    fractal_kernel<<<NBLK, 256>>>(img, bounds, out);
}